// round 4
// baseline (speedup 1.0000x reference)
#include <cuda_runtime.h>
#include <math.h>

#define BB   4
#define SS   2048
#define DD   1024
#define HH   16
#define HD   64
#define DFF  4096
#define ROWS (BB*SS)   // 8192

// ---------------- scratch (allocation-free: __device__ globals) ----------------
__device__ float g_h  [ROWS*(size_t)DD];   // LN output (reused for LN1 and LN2)
__device__ float g_q  [ROWS*(size_t)DD];
__device__ float g_k  [ROWS*(size_t)DD];
__device__ float g_v  [ROWS*(size_t)DD];
__device__ float g_ctx[ROWS*(size_t)DD];
__device__ float g_x2 [ROWS*(size_t)DD];   // residual after attention
__device__ float g_ffn[ROWS*(size_t)DFF];

// ---------------- LayerNorm: one block per row, D = 1024 ----------------
__global__ void __launch_bounds__(256) ln_kernel(const float* __restrict__ x,
                                                 const float* __restrict__ sc,
                                                 const float* __restrict__ sh,
                                                 float* __restrict__ out)
{
    const int row = blockIdx.x;
    const float* xr = x + (size_t)row * DD;
    const int c = threadIdx.x * 4;
    float4 v = *(const float4*)(xr + c);
    float s  = v.x + v.y + v.z + v.w;
    float q  = v.x*v.x + v.y*v.y + v.z*v.z + v.w*v.w;
    #pragma unroll
    for (int o = 16; o; o >>= 1) {
        s += __shfl_xor_sync(0xffffffffu, s, o);
        q += __shfl_xor_sync(0xffffffffu, q, o);
    }
    __shared__ float ssum[8], sq[8];
    const int w = threadIdx.x >> 5, ln = threadIdx.x & 31;
    if (ln == 0) { ssum[w] = s; sq[w] = q; }
    __syncthreads();
    float tot = 0.f, totq = 0.f;
    #pragma unroll
    for (int i = 0; i < 8; i++) { tot += ssum[i]; totq += sq[i]; }
    const float mean = tot * (1.0f / DD);
    const float var  = totq * (1.0f / DD) - mean * mean;
    const float inv  = rsqrtf(var + 1e-8f);
    float4 scv = *(const float4*)(sc + c);
    float4 shv = *(const float4*)(sh + c);
    float4 o4;
    o4.x = scv.x * (v.x - mean) * inv + shv.x;
    o4.y = scv.y * (v.y - mean) * inv + shv.y;
    o4.z = scv.z * (v.z - mean) * inv + shv.z;
    o4.w = scv.w * (v.w - mean) * inv + shv.w;
    *(float4*)(out + (size_t)row * DD + c) = o4;
}

// ---------------- GELU (tanh approx, matches reference) ----------------
__device__ __forceinline__ float gelu_f(float x)
{
    float x3 = x * x * x;
    float t  = tanhf(0.7978845608028654f * (x + 0.044715f * x3));
    return 0.5f * x * (1.0f + t);
}

// ---------------- SGEMM 128x128x8, 256 threads, 8x8 per thread ----------------
// C[M,N] = A[M,K] @ B[K,N]   (row-major). M is multiple of 128, N of 128, K of 8.
// MODE 0: plain     MODE 1: + bias + residual     MODE 2: + bias, gelu
template<int MODE>
__global__ void __launch_bounds__(256) sgemm_kernel(
    const float* __restrict__ A, const float* __restrict__ B,
    const float* __restrict__ bias, const float* __restrict__ res,
    float* __restrict__ C, int N, int K)
{
    __shared__ float As[8][132];   // transposed A tile: As[k][m]
    __shared__ float Bs[8][132];

    const int tid = threadIdx.x;
    const int tx  = tid & 15, ty = tid >> 4;
    const int m0  = blockIdx.y * 128, n0 = blockIdx.x * 128;

    float acc[8][8] = {};

    const int arow = tid >> 1, ac4 = (tid & 1) * 4;   // A: 128 rows x 8 cols
    const int brow = tid >> 5, bc4 = (tid & 31) * 4;  // B: 8 rows x 128 cols
    const float* Aptr = A + (size_t)(m0 + arow) * K + ac4;
    const float* Bptr = B + (size_t)brow * N + n0 + bc4;

    for (int k0 = 0; k0 < K; k0 += 8) {
        float4 av = *(const float4*)Aptr;
        float4 bv = *(const float4*)Bptr;
        __syncthreads();                 // previous iteration's compute done
        As[ac4 + 0][arow] = av.x;
        As[ac4 + 1][arow] = av.y;
        As[ac4 + 2][arow] = av.z;
        As[ac4 + 3][arow] = av.w;
        *(float4*)&Bs[brow][bc4] = bv;
        __syncthreads();

        #pragma unroll
        for (int kk = 0; kk < 8; kk++) {
            float a[8], b[8];
            *(float4*)(a)     = *(const float4*)&As[kk][ty * 8];
            *(float4*)(a + 4) = *(const float4*)&As[kk][ty * 8 + 4];
            *(float4*)(b)     = *(const float4*)&Bs[kk][tx * 8];
            *(float4*)(b + 4) = *(const float4*)&Bs[kk][tx * 8 + 4];
            #pragma unroll
            for (int i = 0; i < 8; i++)
                #pragma unroll
                for (int j = 0; j < 8; j++)
                    acc[i][j] = fmaf(a[i], b[j], acc[i][j]);
        }
        Aptr += 8;
        Bptr += (size_t)8 * N;
    }

    #pragma unroll
    for (int i = 0; i < 8; i++) {
        const int row = m0 + ty * 8 + i;
        float* Crow = C + (size_t)row * N + n0 + tx * 8;
        const float* Rrow = (MODE == 1) ? (res + (size_t)row * N + n0 + tx * 8) : nullptr;
        #pragma unroll
        for (int j = 0; j < 8; j++) {
            float v = acc[i][j];
            if (MODE >= 1) v += bias[n0 + tx * 8 + j];
            if (MODE == 2) v = gelu_f(v);
            if (MODE == 1) v += Rrow[j];
            Crow[j] = v;
        }
    }
}

// ---------------- Flash attention, fp32, causal. Hd=64, 64x64 tiles ----------------
// Q/K/V/O layout: [(b*S + s)*D + h*64 + d]  (i.e., [B,S,H,Hd] flattened)
#define ATTN_PITCH 65
#define ATTN_SMEM  (4 * 64 * ATTN_PITCH * 4)

__global__ void __launch_bounds__(256) attn_kernel(
    const float* __restrict__ Q, const float* __restrict__ K,
    const float* __restrict__ V, float* __restrict__ O)
{
    extern __shared__ float smem[];
    float* Qs = smem;
    float* Ks = smem + 64 * ATTN_PITCH;
    float* Vs = smem + 2 * 64 * ATTN_PITCH;
    float* Ps = smem + 3 * 64 * ATTN_PITCH;

    const int bh = blockIdx.y;
    const int b  = bh >> 4, h = bh & 15;
    const int qt = blockIdx.x;
    const int q0 = qt * 64;
    const int tid = threadIdx.x;
    const int tx = tid & 15, ty = tid >> 4;
    const size_t base = (size_t)b * SS * DD + (size_t)h * HD;

    // load Q tile (64 x 64)
    for (int e = tid; e < 64 * 16; e += 256) {
        int r = e >> 4, c4 = (e & 15) * 4;
        float4 v = *(const float4*)(Q + base + (size_t)(q0 + r) * DD + c4);
        Qs[r * ATTN_PITCH + c4 + 0] = v.x;
        Qs[r * ATTN_PITCH + c4 + 1] = v.y;
        Qs[r * ATTN_PITCH + c4 + 2] = v.z;
        Qs[r * ATTN_PITCH + c4 + 3] = v.w;
    }

    float o[4][4] = {};
    float m[4] = {-1e30f, -1e30f, -1e30f, -1e30f};
    float l[4] = {0.f, 0.f, 0.f, 0.f};

    for (int kt = 0; kt <= qt; kt++) {
        const int k0 = kt * 64;
        __syncthreads();   // Qs visible (1st iter) / previous PV done (others)
        for (int e = tid; e < 64 * 16; e += 256) {
            int r = e >> 4, c4 = (e & 15) * 4;
            float4 kv = *(const float4*)(K + base + (size_t)(k0 + r) * DD + c4);
            Ks[r * ATTN_PITCH + c4 + 0] = kv.x;
            Ks[r * ATTN_PITCH + c4 + 1] = kv.y;
            Ks[r * ATTN_PITCH + c4 + 2] = kv.z;
            Ks[r * ATTN_PITCH + c4 + 3] = kv.w;
            float4 vv = *(const float4*)(V + base + (size_t)(k0 + r) * DD + c4);
            Vs[r * ATTN_PITCH + c4 + 0] = vv.x;
            Vs[r * ATTN_PITCH + c4 + 1] = vv.y;
            Vs[r * ATTN_PITCH + c4 + 2] = vv.z;
            Vs[r * ATTN_PITCH + c4 + 3] = vv.w;
        }
        __syncthreads();

        // S = Q @ K^T  (each thread: 4x4 micro-tile)
        float s[4][4] = {};
        #pragma unroll 8
        for (int d = 0; d < 64; d++) {
            float a[4], bb[4];
            #pragma unroll
            for (int r = 0; r < 4; r++) a[r]  = Qs[(ty * 4 + r) * ATTN_PITCH + d];
            #pragma unroll
            for (int c = 0; c < 4; c++) bb[c] = Ks[(tx * 4 + c) * ATTN_PITCH + d];
            #pragma unroll
            for (int r = 0; r < 4; r++)
                #pragma unroll
                for (int c = 0; c < 4; c++)
                    s[r][c] = fmaf(a[r], bb[c], s[r][c]);
        }

        const float sc = 0.125f;  // 1/sqrt(64)
        const bool diag = (kt == qt);
        #pragma unroll
        for (int r = 0; r < 4; r++) {
            const int gi = q0 + ty * 4 + r;
            float mt = -1e30f;
            #pragma unroll
            for (int c = 0; c < 4; c++) {
                float v = s[r][c] * sc;
                if (diag && (k0 + tx * 4 + c) > gi) v = -1e30f;
                s[r][c] = v;
                mt = fmaxf(mt, v);
            }
            #pragma unroll
            for (int off = 8; off; off >>= 1)
                mt = fmaxf(mt, __shfl_xor_sync(0xffffffffu, mt, off));
            const float mnew  = fmaxf(m[r], mt);
            const float alpha = __expf(m[r] - mnew);
            float ps = 0.f;
            #pragma unroll
            for (int c = 0; c < 4; c++) {
                float p = __expf(s[r][c] - mnew);
                Ps[(ty * 4 + r) * ATTN_PITCH + tx * 4 + c] = p;
                ps += p;
            }
            #pragma unroll
            for (int off = 8; off; off >>= 1)
                ps += __shfl_xor_sync(0xffffffffu, ps, off);
            l[r] = l[r] * alpha + ps;
            m[r] = mnew;
            #pragma unroll
            for (int c = 0; c < 4; c++) o[r][c] *= alpha;
        }
        __syncthreads();

        // O += P @ V
        #pragma unroll 8
        for (int d = 0; d < 64; d++) {
            float pa[4], vb[4];
            #pragma unroll
            for (int r = 0; r < 4; r++) pa[r] = Ps[(ty * 4 + r) * ATTN_PITCH + d];
            #pragma unroll
            for (int c = 0; c < 4; c++) vb[c] = Vs[d * ATTN_PITCH + tx * 4 + c];
            #pragma unroll
            for (int r = 0; r < 4; r++)
                #pragma unroll
                for (int c = 0; c < 4; c++)
                    o[r][c] = fmaf(pa[r], vb[c], o[r][c]);
        }
    }

    #pragma unroll
    for (int r = 0; r < 4; r++) {
        const float inv = 1.0f / l[r];
        const int gi = q0 + ty * 4 + r;
        float* op = O + base + (size_t)gi * DD + tx * 4;
        #pragma unroll
        for (int c = 0; c < 4; c++) op[c] = o[r][c] * inv;
    }
}

// ---------------- launch ----------------
extern "C" void kernel_launch(void* const* d_in, const int* in_sizes, int n_in,
                              void* d_out, int out_size)
{
    const float* x    = (const float*)d_in[0];
    const float* Wq   = (const float*)d_in[1];
    const float* Wk   = (const float*)d_in[2];
    const float* Wv   = (const float*)d_in[3];
    const float* Wo   = (const float*)d_in[4];
    const float* bo   = (const float*)d_in[5];
    const float* W1   = (const float*)d_in[6];
    const float* b1   = (const float*)d_in[7];
    const float* W2   = (const float*)d_in[8];
    const float* b2   = (const float*)d_in[9];
    const float* ln1s = (const float*)d_in[10];
    const float* ln1b = (const float*)d_in[11];
    const float* ln2s = (const float*)d_in[12];
    const float* ln2b = (const float*)d_in[13];
    float* out = (float*)d_out;

    float *h, *q, *k, *v, *ctx, *x2, *ffn;
    cudaGetSymbolAddress((void**)&h,   g_h);
    cudaGetSymbolAddress((void**)&q,   g_q);
    cudaGetSymbolAddress((void**)&k,   g_k);
    cudaGetSymbolAddress((void**)&v,   g_v);
    cudaGetSymbolAddress((void**)&ctx, g_ctx);
    cudaGetSymbolAddress((void**)&x2,  g_x2);
    cudaGetSymbolAddress((void**)&ffn, g_ffn);

    cudaFuncSetAttribute(attn_kernel, cudaFuncAttributeMaxDynamicSharedMemorySize, ATTN_SMEM);

    // 1) LN1
    ln_kernel<<<ROWS, 256>>>(x, ln1s, ln1b, h);

    // 2) QKV projections
    dim3 gD(DD / 128, ROWS / 128);
    sgemm_kernel<0><<<gD, 256>>>(h, Wq, nullptr, nullptr, q, DD, DD);
    sgemm_kernel<0><<<gD, 256>>>(h, Wk, nullptr, nullptr, k, DD, DD);
    sgemm_kernel<0><<<gD, 256>>>(h, Wv, nullptr, nullptr, v, DD, DD);

    // 3) causal flash attention
    dim3 gA(SS / 64, BB * HH);
    attn_kernel<<<gA, 256, ATTN_SMEM>>>(q, k, v, ctx);

    // 4) output projection + bias + residual
    sgemm_kernel<1><<<gD, 256>>>(ctx, Wo, bo, x, x2, DD, DD);

    // 5) LN2
    ln_kernel<<<ROWS, 256>>>(x2, ln2s, ln2b, h);

    // 6) FFN up + gelu
    dim3 gF(DFF / 128, ROWS / 128);
    sgemm_kernel<2><<<gF, 256>>>(h, W1, b1, nullptr, ffn, DFF, DD);

    // 7) FFN down + bias + residual -> output
    sgemm_kernel<1><<<gD, 256>>>(ffn, W2, b2, x2, out, DD, DFF);
}

// round 9
// speedup vs baseline: 1.5091x; 1.5091x over previous
#include <cuda_runtime.h>
#include <cuda_bf16.h>
#include <math.h>
#include <cstdint>

#define BB   4
#define SS   2048
#define DD   1024
#define HH   16
#define HD   64
#define DFF  4096
#define ROWS (BB*SS)   // 8192

// ---------------- scratch (allocation-free: __device__ globals) ----------------
__device__ float g_h  [ROWS*(size_t)DD];
__device__ float g_q  [ROWS*(size_t)DD];
__device__ float g_k  [ROWS*(size_t)DD];
__device__ float g_v  [ROWS*(size_t)DD];
__device__ float g_ctx[ROWS*(size_t)DD];
__device__ float g_x2 [ROWS*(size_t)DD];
__device__ float g_ffn[ROWS*(size_t)DFF];
__device__ __nv_bfloat16 g_ahi[ROWS*(size_t)DFF];   // activation split (hi)
__device__ __nv_bfloat16 g_alo[ROWS*(size_t)DFF];   // activation split (lo)
__device__ __nv_bfloat16 g_whi[DD*(size_t)DFF];     // weight^T split (hi)  [N,K]
__device__ __nv_bfloat16 g_wlo[DD*(size_t)DFF];     // weight^T split (lo)  [N,K]

__device__ __forceinline__ uint32_t smem_to_u32(const void* p) {
    uint32_t a;
    asm("{ .reg .u64 t; cvta.to.shared.u64 t, %1; cvt.u32.u64 %0, t; }" : "=r"(a) : "l"(p));
    return a;
}

// ---------------- LayerNorm ----------------
__global__ void __launch_bounds__(256) ln_kernel(const float* __restrict__ x,
                                                 const float* __restrict__ sc,
                                                 const float* __restrict__ sh,
                                                 float* __restrict__ out)
{
    const int row = blockIdx.x;
    const float* xr = x + (size_t)row * DD;
    const int c = threadIdx.x * 4;
    float4 v = *(const float4*)(xr + c);
    float s  = v.x + v.y + v.z + v.w;
    float q  = v.x*v.x + v.y*v.y + v.z*v.z + v.w*v.w;
    #pragma unroll
    for (int o = 16; o; o >>= 1) {
        s += __shfl_xor_sync(0xffffffffu, s, o);
        q += __shfl_xor_sync(0xffffffffu, q, o);
    }
    __shared__ float ssum[8], sq[8];
    const int w = threadIdx.x >> 5, ln = threadIdx.x & 31;
    if (ln == 0) { ssum[w] = s; sq[w] = q; }
    __syncthreads();
    float tot = 0.f, totq = 0.f;
    #pragma unroll
    for (int i = 0; i < 8; i++) { tot += ssum[i]; totq += sq[i]; }
    const float mean = tot * (1.0f / DD);
    const float var  = totq * (1.0f / DD) - mean * mean;
    const float inv  = rsqrtf(var + 1e-8f);
    float4 scv = *(const float4*)(sc + c);
    float4 shv = *(const float4*)(sh + c);
    float4 o4;
    o4.x = scv.x * (v.x - mean) * inv + shv.x;
    o4.y = scv.y * (v.y - mean) * inv + shv.y;
    o4.z = scv.z * (v.z - mean) * inv + shv.z;
    o4.w = scv.w * (v.w - mean) * inv + shv.w;
    *(float4*)(out + (size_t)row * DD + c) = o4;
}

__device__ __forceinline__ float gelu_f(float x)
{
    float x3 = x * x * x;
    float t  = tanhf(0.7978845608028654f * (x + 0.044715f * x3));
    return 0.5f * x * (1.0f + t);
}

// ---------------- split fp32 -> bf16 hi/lo ----------------
__global__ void __launch_bounds__(256) act_split(const float* __restrict__ x,
                                                 __nv_bfloat16* __restrict__ hi,
                                                 __nv_bfloat16* __restrict__ lo)
{
    const int i = blockIdx.x * 256 + threadIdx.x;   // one float4 per thread
    float4 v = ((const float4*)x)[i];
    __nv_bfloat16 h0 = __float2bfloat16(v.x), h1 = __float2bfloat16(v.y);
    __nv_bfloat16 h2 = __float2bfloat16(v.z), h3 = __float2bfloat16(v.w);
    __nv_bfloat16 l0 = __float2bfloat16(v.x - __bfloat162float(h0));
    __nv_bfloat16 l1 = __float2bfloat16(v.y - __bfloat162float(h1));
    __nv_bfloat16 l2 = __float2bfloat16(v.z - __bfloat162float(h2));
    __nv_bfloat16 l3 = __float2bfloat16(v.w - __bfloat162float(h3));
    ((__nv_bfloat162*)hi)[2*i]   = __halves2bfloat162(h0, h1);
    ((__nv_bfloat162*)hi)[2*i+1] = __halves2bfloat162(h2, h3);
    ((__nv_bfloat162*)lo)[2*i]   = __halves2bfloat162(l0, l1);
    ((__nv_bfloat162*)lo)[2*i+1] = __halves2bfloat162(l2, l3);
}

// ---------------- split + transpose weights: W[K,N] fp32 -> hiT/loT [N,K] bf16 --------
__global__ void __launch_bounds__(256) wt_split_T(const float* __restrict__ W,
                                                  __nv_bfloat16* __restrict__ hiT,
                                                  __nv_bfloat16* __restrict__ loT,
                                                  int K, int N)
{
    __shared__ float t[32][33];
    const int n0 = blockIdx.x * 32, k0 = blockIdx.y * 32;
    const int tx = threadIdx.x & 31, ty = threadIdx.x >> 5;
    #pragma unroll
    for (int i = ty; i < 32; i += 8)
        t[i][tx] = W[(size_t)(k0 + i) * N + n0 + tx];   // t[k][n]
    __syncthreads();
    #pragma unroll
    for (int i = ty; i < 32; i += 8) {
        float v = t[tx][i];                              // = W[k0+tx][n0+i]
        __nv_bfloat16 h = __float2bfloat16(v);
        __nv_bfloat16 l = __float2bfloat16(v - __bfloat162float(h));
        const size_t o = (size_t)(n0 + i) * K + k0 + tx;
        hiT[o] = h;  loT[o] = l;
    }
}

// ================= warp-MMA GEMM (portable PTX: ldmatrix + mma.sync bf16) =======
// C[M,N] = A[M,K] @ B[K,N], B supplied transposed as BT[N,K].
// 3-term split: C = Ah*Bh + Ah*Bl + Al*Bh.
// CTA tile 128x128, BK=32, 8 warps (4 along M x 2 along N), warp tile 32x64.
// MODE 0: plain   MODE 1: +bias +residual   MODE 2: +bias, gelu

#define PB   40                      // smem pitch in bf16 elems (80B rows: conflict-free ldmatrix)
#define TILE_E (128 * PB)            // elems per tile
#define TILE_B (TILE_E * 2)          // bytes per tile (10240)
#define STAGE_B (4 * TILE_B)         // Ah, Al, Bh, Bl
#define MM_SMEM (2 * STAGE_B)        // double buffered (81920)

__device__ __forceinline__ void ldmx4(uint32_t* r, uint32_t addr) {
    asm volatile("ldmatrix.sync.aligned.m8n8.x4.shared.b16 {%0,%1,%2,%3}, [%4];"
        : "=r"(r[0]), "=r"(r[1]), "=r"(r[2]), "=r"(r[3]) : "r"(addr));
}
__device__ __forceinline__ void ldmx2(uint32_t* r, uint32_t addr) {
    asm volatile("ldmatrix.sync.aligned.m8n8.x2.shared.b16 {%0,%1}, [%2];"
        : "=r"(r[0]), "=r"(r[1]) : "r"(addr));
}
__device__ __forceinline__ void mma16816(float* c, const uint32_t* a, const uint32_t* b) {
    asm volatile("mma.sync.aligned.m16n8k16.row.col.f32.bf16.bf16.f32 "
        "{%0,%1,%2,%3}, {%4,%5,%6,%7}, {%8,%9}, {%0,%1,%2,%3};"
        : "+f"(c[0]), "+f"(c[1]), "+f"(c[2]), "+f"(c[3])
        : "r"(a[0]), "r"(a[1]), "r"(a[2]), "r"(a[3]), "r"(b[0]), "r"(b[1]));
}

template<int MODE>
__global__ void __launch_bounds__(256) mm_gemm(
    const __nv_bfloat16* __restrict__ Ahi, const __nv_bfloat16* __restrict__ Alo,
    const __nv_bfloat16* __restrict__ BhiT, const __nv_bfloat16* __restrict__ BloT,
    const float* __restrict__ bias, const float* __restrict__ res,
    float* __restrict__ C, int N, int K)
{
    extern __shared__ char smem[];
    const int tid  = threadIdx.x;
    const int lane = tid & 31, wid = tid >> 5;
    const int m0 = blockIdx.y * 128, n0 = blockIdx.x * 128;
    const int wm = (wid & 3) * 32, wn = (wid >> 2) * 64;

    const uint32_t sb = smem_to_u32(smem);

    // global load indices: per tile 512 uint4 (8 bf16 each); thread does idx=tid, tid+256
    // row = idx>>2, col8 = (idx&3)*8
    const int r0g = tid >> 2,        c0g = (tid & 3) * 8;
    const int r1g = (tid + 256) >> 2, c1g = ((tid + 256) & 3) * 8;

    float acc[2][8][4];
    #pragma unroll
    for (int i = 0; i < 2; i++)
        #pragma unroll
        for (int j = 0; j < 8; j++)
            #pragma unroll
            for (int e = 0; e < 4; e++) acc[i][j][e] = 0.f;

    const int nch = K >> 5;

    // -------- load one chunk into stage buffer --------
    auto load_chunk = [&](int c, int buf) {
        const int k0 = c << 5;
        char* st = smem + buf * STAGE_B;
        const __nv_bfloat16* aH = Ahi  + (size_t)m0 * K + k0;
        const __nv_bfloat16* aL = Alo  + (size_t)m0 * K + k0;
        const __nv_bfloat16* bH = BhiT + (size_t)n0 * K + k0;
        const __nv_bfloat16* bL = BloT + (size_t)n0 * K + k0;
        // two positions per tile
        {
            const size_t g0 = (size_t)r0g * K + c0g;
            const size_t g1 = (size_t)r1g * K + c1g;
            const uint32_t s0 = (uint32_t)(r0g * PB + c0g) * 2;
            const uint32_t s1 = (uint32_t)(r1g * PB + c1g) * 2;
            *(uint4*)(st + 0*TILE_B + s0) = *(const uint4*)(aH + g0);
            *(uint4*)(st + 0*TILE_B + s1) = *(const uint4*)(aH + g1);
            *(uint4*)(st + 1*TILE_B + s0) = *(const uint4*)(aL + g0);
            *(uint4*)(st + 1*TILE_B + s1) = *(const uint4*)(aL + g1);
            *(uint4*)(st + 2*TILE_B + s0) = *(const uint4*)(bH + g0);
            *(uint4*)(st + 2*TILE_B + s1) = *(const uint4*)(bH + g1);
            *(uint4*)(st + 3*TILE_B + s0) = *(const uint4*)(bL + g0);
            *(uint4*)(st + 3*TILE_B + s1) = *(const uint4*)(bL + g1);
        }
    };

    load_chunk(0, 0);
    __syncthreads();

    for (int c = 0; c < nch; ++c) {
        const int buf = c & 1;
        if (c + 1 < nch) load_chunk(c + 1, buf ^ 1);

        const uint32_t stA_h = sb + buf * STAGE_B;
        const uint32_t stA_l = stA_h + TILE_B;
        const uint32_t stB_h = stA_h + 2 * TILE_B;
        const uint32_t stB_l = stA_h + 3 * TILE_B;

        // per-lane ldmatrix offsets (elements)
        const uint32_t aoff = (uint32_t)((wm + (lane & 15)) * PB + (lane >> 4) * 8) * 2;
        const uint32_t boff = (uint32_t)((wn + (lane & 7)) * PB + ((lane >> 3) & 1) * 8) * 2;

        #pragma unroll
        for (int ks = 0; ks < 2; ks++) {
            const uint32_t kso = (uint32_t)(ks * 16) * 2;
            uint32_t aH[2][4], aL[2][4], bH[8][2], bL[8][2];
            #pragma unroll
            for (int i = 0; i < 2; i++) {
                ldmx4(aH[i], stA_h + aoff + kso + (uint32_t)(i * 16 * PB) * 2);
                ldmx4(aL[i], stA_l + aoff + kso + (uint32_t)(i * 16 * PB) * 2);
            }
            #pragma unroll
            for (int j = 0; j < 8; j++) {
                ldmx2(bH[j], stB_h + boff + kso + (uint32_t)(j * 8 * PB) * 2);
                ldmx2(bL[j], stB_l + boff + kso + (uint32_t)(j * 8 * PB) * 2);
            }
            #pragma unroll
            for (int i = 0; i < 2; i++)
                #pragma unroll
                for (int j = 0; j < 8; j++) {
                    mma16816(acc[i][j], aH[i], bH[j]);
                    mma16816(acc[i][j], aH[i], bL[j]);
                    mma16816(acc[i][j], aL[i], bH[j]);
                }
        }
        __syncthreads();
    }

    // -------- epilogue: direct float2 stores from C fragments --------
    #pragma unroll
    for (int i = 0; i < 2; i++) {
        const int r = m0 + wm + i * 16 + (lane >> 2);
        #pragma unroll
        for (int j = 0; j < 8; j++) {
            const int col = n0 + wn + j * 8 + (lane & 3) * 2;
            float v0 = acc[i][j][0], v1 = acc[i][j][1];
            float v2 = acc[i][j][2], v3 = acc[i][j][3];
            if (MODE >= 1) {
                float2 bb = *(const float2*)(bias + col);
                v0 += bb.x; v1 += bb.y; v2 += bb.x; v3 += bb.y;
            }
            if (MODE == 2) { v0 = gelu_f(v0); v1 = gelu_f(v1); v2 = gelu_f(v2); v3 = gelu_f(v3); }
            if (MODE == 1) {
                float2 r0v = *(const float2*)(res + (size_t)r * N + col);
                float2 r1v = *(const float2*)(res + (size_t)(r + 8) * N + col);
                v0 += r0v.x; v1 += r0v.y; v2 += r1v.x; v3 += r1v.y;
            }
            float2 o0 = make_float2(v0, v1), o1 = make_float2(v2, v3);
            *(float2*)(C + (size_t)r * N + col)       = o0;
            *(float2*)(C + (size_t)(r + 8) * N + col) = o1;
        }
    }
}

// ---------------- Flash attention, fp32, causal. Hd=64, 64x64 tiles ----------------
#define ATTN_PITCH 65
#define ATTN_SMEM  (4 * 64 * ATTN_PITCH * 4)

__global__ void __launch_bounds__(256) attn_kernel(
    const float* __restrict__ Q, const float* __restrict__ K,
    const float* __restrict__ V, float* __restrict__ O)
{
    extern __shared__ float asmem[];
    float* Qs = asmem;
    float* Ks = asmem + 64 * ATTN_PITCH;
    float* Vs = asmem + 2 * 64 * ATTN_PITCH;
    float* Ps = asmem + 3 * 64 * ATTN_PITCH;

    const int bh = blockIdx.y;
    const int b  = bh >> 4, h = bh & 15;
    const int qt = blockIdx.x;
    const int q0 = qt * 64;
    const int tid = threadIdx.x;
    const int tx = tid & 15, ty = tid >> 4;
    const size_t base = (size_t)b * SS * DD + (size_t)h * HD;

    for (int e = tid; e < 64 * 16; e += 256) {
        int r = e >> 4, c4 = (e & 15) * 4;
        float4 v = *(const float4*)(Q + base + (size_t)(q0 + r) * DD + c4);
        Qs[r * ATTN_PITCH + c4 + 0] = v.x;
        Qs[r * ATTN_PITCH + c4 + 1] = v.y;
        Qs[r * ATTN_PITCH + c4 + 2] = v.z;
        Qs[r * ATTN_PITCH + c4 + 3] = v.w;
    }

    float o[4][4] = {};
    float m[4] = {-1e30f, -1e30f, -1e30f, -1e30f};
    float l[4] = {0.f, 0.f, 0.f, 0.f};

    for (int kt = 0; kt <= qt; kt++) {
        const int k0 = kt * 64;
        __syncthreads();
        for (int e = tid; e < 64 * 16; e += 256) {
            int r = e >> 4, c4 = (e & 15) * 4;
            float4 kv = *(const float4*)(K + base + (size_t)(k0 + r) * DD + c4);
            Ks[r * ATTN_PITCH + c4 + 0] = kv.x;
            Ks[r * ATTN_PITCH + c4 + 1] = kv.y;
            Ks[r * ATTN_PITCH + c4 + 2] = kv.z;
            Ks[r * ATTN_PITCH + c4 + 3] = kv.w;
            float4 vv = *(const float4*)(V + base + (size_t)(k0 + r) * DD + c4);
            Vs[r * ATTN_PITCH + c4 + 0] = vv.x;
            Vs[r * ATTN_PITCH + c4 + 1] = vv.y;
            Vs[r * ATTN_PITCH + c4 + 2] = vv.z;
            Vs[r * ATTN_PITCH + c4 + 3] = vv.w;
        }
        __syncthreads();

        float s[4][4] = {};
        #pragma unroll 8
        for (int d = 0; d < 64; d++) {
            float a[4], bb[4];
            #pragma unroll
            for (int r = 0; r < 4; r++) a[r]  = Qs[(ty * 4 + r) * ATTN_PITCH + d];
            #pragma unroll
            for (int c = 0; c < 4; c++) bb[c] = Ks[(tx * 4 + c) * ATTN_PITCH + d];
            #pragma unroll
            for (int r = 0; r < 4; r++)
                #pragma unroll
                for (int c = 0; c < 4; c++)
                    s[r][c] = fmaf(a[r], bb[c], s[r][c]);
        }

        const float sc = 0.125f;
        const bool diag = (kt == qt);
        #pragma unroll
        for (int r = 0; r < 4; r++) {
            const int gi = q0 + ty * 4 + r;
            float mt = -1e30f;
            #pragma unroll
            for (int c = 0; c < 4; c++) {
                float v = s[r][c] * sc;
                if (diag && (k0 + tx * 4 + c) > gi) v = -1e30f;
                s[r][c] = v;
                mt = fmaxf(mt, v);
            }
            #pragma unroll
            for (int off = 8; off; off >>= 1)
                mt = fmaxf(mt, __shfl_xor_sync(0xffffffffu, mt, off));
            const float mnew  = fmaxf(m[r], mt);
            const float alpha = __expf(m[r] - mnew);
            float ps = 0.f;
            #pragma unroll
            for (int c = 0; c < 4; c++) {
                float p = __expf(s[r][c] - mnew);
                Ps[(ty * 4 + r) * ATTN_PITCH + tx * 4 + c] = p;
                ps += p;
            }
            #pragma unroll
            for (int off = 8; off; off >>= 1)
                ps += __shfl_xor_sync(0xffffffffu, ps, off);
            l[r] = l[r] * alpha + ps;
            m[r] = mnew;
            #pragma unroll
            for (int c = 0; c < 4; c++) o[r][c] *= alpha;
        }
        __syncthreads();

        #pragma unroll 8
        for (int d = 0; d < 64; d++) {
            float pa[4], vb[4];
            #pragma unroll
            for (int r = 0; r < 4; r++) pa[r] = Ps[(ty * 4 + r) * ATTN_PITCH + d];
            #pragma unroll
            for (int c = 0; c < 4; c++) vb[c] = Vs[d * ATTN_PITCH + tx * 4 + c];
            #pragma unroll
            for (int r = 0; r < 4; r++)
                #pragma unroll
                for (int c = 0; c < 4; c++)
                    o[r][c] = fmaf(pa[r], vb[c], o[r][c]);
        }
    }

    #pragma unroll
    for (int r = 0; r < 4; r++) {
        const float inv = 1.0f / l[r];
        const int gi = q0 + ty * 4 + r;
        float* op = O + base + (size_t)gi * DD + tx * 4;
        #pragma unroll
        for (int c = 0; c < 4; c++) op[c] = o[r][c] * inv;
    }
}

// ---------------- launch ----------------
extern "C" void kernel_launch(void* const* d_in, const int* in_sizes, int n_in,
                              void* d_out, int out_size)
{
    const float* x    = (const float*)d_in[0];
    const float* Wq   = (const float*)d_in[1];
    const float* Wk   = (const float*)d_in[2];
    const float* Wv   = (const float*)d_in[3];
    const float* Wo   = (const float*)d_in[4];
    const float* bo   = (const float*)d_in[5];
    const float* W1   = (const float*)d_in[6];
    const float* b1   = (const float*)d_in[7];
    const float* W2   = (const float*)d_in[8];
    const float* b2   = (const float*)d_in[9];
    const float* ln1s = (const float*)d_in[10];
    const float* ln1b = (const float*)d_in[11];
    const float* ln2s = (const float*)d_in[12];
    const float* ln2b = (const float*)d_in[13];
    float* out = (float*)d_out;

    float *h, *q, *k, *v, *ctx, *x2, *ffn;
    __nv_bfloat16 *ahi, *alo, *whi, *wlo;
    cudaGetSymbolAddress((void**)&h,   g_h);
    cudaGetSymbolAddress((void**)&q,   g_q);
    cudaGetSymbolAddress((void**)&k,   g_k);
    cudaGetSymbolAddress((void**)&v,   g_v);
    cudaGetSymbolAddress((void**)&ctx, g_ctx);
    cudaGetSymbolAddress((void**)&x2,  g_x2);
    cudaGetSymbolAddress((void**)&ffn, g_ffn);
    cudaGetSymbolAddress((void**)&ahi, g_ahi);
    cudaGetSymbolAddress((void**)&alo, g_alo);
    cudaGetSymbolAddress((void**)&whi, g_whi);
    cudaGetSymbolAddress((void**)&wlo, g_wlo);

    cudaFuncSetAttribute(attn_kernel, cudaFuncAttributeMaxDynamicSharedMemorySize, ATTN_SMEM);
    cudaFuncSetAttribute(mm_gemm<0>, cudaFuncAttributeMaxDynamicSharedMemorySize, MM_SMEM);
    cudaFuncSetAttribute(mm_gemm<1>, cudaFuncAttributeMaxDynamicSharedMemorySize, MM_SMEM);
    cudaFuncSetAttribute(mm_gemm<2>, cudaFuncAttributeMaxDynamicSharedMemorySize, MM_SMEM);

    const dim3 gD(DD / 128, ROWS / 128);     // N=1024 output gemms
    const dim3 gF(DFF / 128, ROWS / 128);    // N=4096 output gemm
    const dim3 tWd(DD / 32, DD / 32);        // weight transpose D x D
    const dim3 tW1(DFF / 32, DD / 32);       // W1: K=1024, N=4096
    const dim3 tW2(DD / 32, DFF / 32);       // W2: K=4096, N=1024

    // 1) LN1 + activation split
    ln_kernel<<<ROWS, 256>>>(x, ln1s, ln1b, h);
    act_split<<<(ROWS * DD) / 1024, 256>>>(h, ahi, alo);

    // 2) QKV projections
    wt_split_T<<<tWd, 256>>>(Wq, whi, wlo, DD, DD);
    mm_gemm<0><<<gD, 256, MM_SMEM>>>(ahi, alo, whi, wlo, nullptr, nullptr, q, DD, DD);
    wt_split_T<<<tWd, 256>>>(Wk, whi, wlo, DD, DD);
    mm_gemm<0><<<gD, 256, MM_SMEM>>>(ahi, alo, whi, wlo, nullptr, nullptr, k, DD, DD);
    wt_split_T<<<tWd, 256>>>(Wv, whi, wlo, DD, DD);
    mm_gemm<0><<<gD, 256, MM_SMEM>>>(ahi, alo, whi, wlo, nullptr, nullptr, v, DD, DD);

    // 3) causal flash attention
    dim3 gA(SS / 64, BB * HH);
    attn_kernel<<<gA, 256, ATTN_SMEM>>>(q, k, v, ctx);

    // 4) output projection + bias + residual
    act_split<<<(ROWS * DD) / 1024, 256>>>(ctx, ahi, alo);
    wt_split_T<<<tWd, 256>>>(Wo, whi, wlo, DD, DD);
    mm_gemm<1><<<gD, 256, MM_SMEM>>>(ahi, alo, whi, wlo, bo, x, x2, DD, DD);

    // 5) LN2 + split
    ln_kernel<<<ROWS, 256>>>(x2, ln2s, ln2b, h);
    act_split<<<(ROWS * DD) / 1024, 256>>>(h, ahi, alo);

    // 6) FFN up + gelu
    wt_split_T<<<tW1, 256>>>(W1, whi, wlo, DD, DFF);
    mm_gemm<2><<<gF, 256, MM_SMEM>>>(ahi, alo, whi, wlo, b1, nullptr, ffn, DFF, DD);

    // 7) FFN down + bias + residual -> output
    act_split<<<(ROWS * DFF) / 1024, 256>>>(ffn, ahi, alo);
    wt_split_T<<<tW2, 256>>>(W2, whi, wlo, DFF, DD);
    mm_gemm<1><<<gD, 256, MM_SMEM>>>(ahi, alo, whi, wlo, b2, x2, out, DD, DFF);
}

// round 11
// speedup vs baseline: 2.0524x; 1.3600x over previous
#include <cuda_runtime.h>
#include <cuda_bf16.h>
#include <math.h>
#include <cstdint>

#define BB   4
#define SS   2048
#define DD   1024
#define HH   16
#define HD   64
#define DFF  4096
#define ROWS (BB*SS)   // 8192
#define QKVS 3072      // packed q|k|v row stride

// ---------------- scratch (allocation-free: __device__ globals) ----------------
__device__ float g_ctx[ROWS*(size_t)DD];
__device__ float g_x2 [ROWS*(size_t)DD];
__device__ float g_ffn[ROWS*(size_t)DFF];           // also holds packed qkv (ROWS x 3072)
__device__ __nv_bfloat16 g_ahi[ROWS*(size_t)DFF];   // activation split (hi)
__device__ __nv_bfloat16 g_alo[ROWS*(size_t)DFF];   // activation split (lo)
__device__ __nv_bfloat16 g_whi[DD*(size_t)DFF];     // weight^T split (hi)  [N,K]
__device__ __nv_bfloat16 g_wlo[DD*(size_t)DFF];     // weight^T split (lo)  [N,K]

__device__ __forceinline__ uint32_t smem_to_u32(const void* p) {
    uint32_t a;
    asm("{ .reg .u64 t; cvta.to.shared.u64 t, %1; cvt.u32.u64 %0, t; }" : "=r"(a) : "l"(p));
    return a;
}
#define CP_ASYNC16(sa, gp) \
    asm volatile("cp.async.cg.shared.global [%0], [%1], 16;" :: "r"(sa), "l"(gp))
#define CP_COMMIT() asm volatile("cp.async.commit_group;" ::: "memory")
#define CP_WAIT(n)  asm volatile("cp.async.wait_group %0;" :: "n"(n) : "memory")

// ---------------- fused LayerNorm + bf16 hi/lo split ----------------
__global__ void __launch_bounds__(256) ln_split(const float* __restrict__ x,
                                                const float* __restrict__ sc,
                                                const float* __restrict__ sh,
                                                __nv_bfloat16* __restrict__ hi,
                                                __nv_bfloat16* __restrict__ lo)
{
    const int row = blockIdx.x;
    const float* xr = x + (size_t)row * DD;
    const int c = threadIdx.x * 4;
    float4 v = *(const float4*)(xr + c);
    float s  = v.x + v.y + v.z + v.w;
    float q  = v.x*v.x + v.y*v.y + v.z*v.z + v.w*v.w;
    #pragma unroll
    for (int o = 16; o; o >>= 1) {
        s += __shfl_xor_sync(0xffffffffu, s, o);
        q += __shfl_xor_sync(0xffffffffu, q, o);
    }
    __shared__ float ssum[8], sq[8];
    const int w = threadIdx.x >> 5, ln = threadIdx.x & 31;
    if (ln == 0) { ssum[w] = s; sq[w] = q; }
    __syncthreads();
    float tot = 0.f, totq = 0.f;
    #pragma unroll
    for (int i = 0; i < 8; i++) { tot += ssum[i]; totq += sq[i]; }
    const float mean = tot * (1.0f / DD);
    const float var  = totq * (1.0f / DD) - mean * mean;
    const float inv  = rsqrtf(var + 1e-8f);
    float4 scv = *(const float4*)(sc + c);
    float4 shv = *(const float4*)(sh + c);
    float o0 = scv.x * (v.x - mean) * inv + shv.x;
    float o1 = scv.y * (v.y - mean) * inv + shv.y;
    float o2 = scv.z * (v.z - mean) * inv + shv.z;
    float o3 = scv.w * (v.w - mean) * inv + shv.w;
    __nv_bfloat16 h0 = __float2bfloat16(o0), h1 = __float2bfloat16(o1);
    __nv_bfloat16 h2 = __float2bfloat16(o2), h3 = __float2bfloat16(o3);
    __nv_bfloat16 l0 = __float2bfloat16(o0 - __bfloat162float(h0));
    __nv_bfloat16 l1 = __float2bfloat16(o1 - __bfloat162float(h1));
    __nv_bfloat16 l2 = __float2bfloat16(o2 - __bfloat162float(h2));
    __nv_bfloat16 l3 = __float2bfloat16(o3 - __bfloat162float(h3));
    const size_t off = (size_t)row * DD + c;
    *(__nv_bfloat162*)(hi + off)     = __halves2bfloat162(h0, h1);
    *(__nv_bfloat162*)(hi + off + 2) = __halves2bfloat162(h2, h3);
    *(__nv_bfloat162*)(lo + off)     = __halves2bfloat162(l0, l1);
    *(__nv_bfloat162*)(lo + off + 2) = __halves2bfloat162(l2, l3);
}

__device__ __forceinline__ float gelu_f(float x)
{
    float x3 = x * x * x;
    float t  = tanhf(0.7978845608028654f * (x + 0.044715f * x3));
    return 0.5f * x * (1.0f + t);
}

// ---------------- split fp32 -> bf16 hi/lo ----------------
__global__ void __launch_bounds__(256) act_split(const float* __restrict__ x,
                                                 __nv_bfloat16* __restrict__ hi,
                                                 __nv_bfloat16* __restrict__ lo)
{
    const int i = blockIdx.x * 256 + threadIdx.x;   // one float4 per thread
    float4 v = ((const float4*)x)[i];
    __nv_bfloat16 h0 = __float2bfloat16(v.x), h1 = __float2bfloat16(v.y);
    __nv_bfloat16 h2 = __float2bfloat16(v.z), h3 = __float2bfloat16(v.w);
    __nv_bfloat16 l0 = __float2bfloat16(v.x - __bfloat162float(h0));
    __nv_bfloat16 l1 = __float2bfloat16(v.y - __bfloat162float(h1));
    __nv_bfloat16 l2 = __float2bfloat16(v.z - __bfloat162float(h2));
    __nv_bfloat16 l3 = __float2bfloat16(v.w - __bfloat162float(h3));
    ((__nv_bfloat162*)hi)[2*i]   = __halves2bfloat162(h0, h1);
    ((__nv_bfloat162*)hi)[2*i+1] = __halves2bfloat162(h2, h3);
    ((__nv_bfloat162*)lo)[2*i]   = __halves2bfloat162(l0, l1);
    ((__nv_bfloat162*)lo)[2*i+1] = __halves2bfloat162(l2, l3);
}

// ---------------- split + transpose weights: W[K,N] fp32 -> hiT/loT [N,K] bf16 --------
__global__ void __launch_bounds__(256) wt_split_T(const float* __restrict__ W,
                                                  __nv_bfloat16* __restrict__ hiT,
                                                  __nv_bfloat16* __restrict__ loT,
                                                  int K, int N)
{
    __shared__ float t[32][33];
    const int n0 = blockIdx.x * 32, k0 = blockIdx.y * 32;
    const int tx = threadIdx.x & 31, ty = threadIdx.x >> 5;
    #pragma unroll
    for (int i = ty; i < 32; i += 8)
        t[i][tx] = W[(size_t)(k0 + i) * N + n0 + tx];   // t[k][n]
    __syncthreads();
    #pragma unroll
    for (int i = ty; i < 32; i += 8) {
        float v = t[tx][i];                              // = W[k0+tx][n0+i]
        __nv_bfloat16 h = __float2bfloat16(v);
        __nv_bfloat16 l = __float2bfloat16(v - __bfloat162float(h));
        const size_t o = (size_t)(n0 + i) * K + k0 + tx;
        hiT[o] = h;  loT[o] = l;
    }
}

// ================= warp-MMA GEMM (ldmatrix + mma.sync bf16, cp.async pipeline) =====
// C[M,N] = A[M,K] @ B[K,N], B supplied transposed as BT[N,K]. 3-term split.
// CTA tile 128x128, BK=32, 8 warps (4 M x 2 N), warp tile 32x64, 2 CTAs/SM.
// MODE 0: plain   MODE 1: +bias +residual   MODE 2: +bias, gelu

#define PB   40                      // smem pitch in bf16 elems (80B rows)
#define TILE_B (128 * PB * 2)        // bytes per tile (10240)
#define STAGE_B (4 * TILE_B)         // Ah, Al, Bh, Bl (40960)
#define MM_SMEM (2 * STAGE_B)        // double buffered (81920)

__device__ __forceinline__ void ldmx4(uint32_t* r, uint32_t addr) {
    asm volatile("ldmatrix.sync.aligned.m8n8.x4.shared.b16 {%0,%1,%2,%3}, [%4];"
        : "=r"(r[0]), "=r"(r[1]), "=r"(r[2]), "=r"(r[3]) : "r"(addr));
}
__device__ __forceinline__ void ldmx2(uint32_t* r, uint32_t addr) {
    asm volatile("ldmatrix.sync.aligned.m8n8.x2.shared.b16 {%0,%1}, [%2];"
        : "=r"(r[0]), "=r"(r[1]) : "r"(addr));
}
__device__ __forceinline__ void mma16816(float* c, const uint32_t* a, const uint32_t* b) {
    asm volatile("mma.sync.aligned.m16n8k16.row.col.f32.bf16.bf16.f32 "
        "{%0,%1,%2,%3}, {%4,%5,%6,%7}, {%8,%9}, {%0,%1,%2,%3};"
        : "+f"(c[0]), "+f"(c[1]), "+f"(c[2]), "+f"(c[3])
        : "r"(a[0]), "r"(a[1]), "r"(a[2]), "r"(a[3]), "r"(b[0]), "r"(b[1]));
}

template<int MODE>
__global__ void __launch_bounds__(256, 2) mm_gemm(
    const __nv_bfloat16* __restrict__ Ahi, const __nv_bfloat16* __restrict__ Alo,
    const __nv_bfloat16* __restrict__ BhiT, const __nv_bfloat16* __restrict__ BloT,
    const float* __restrict__ bias, const float* __restrict__ res,
    float* __restrict__ C, int N, int K)
{
    extern __shared__ char smem[];
    const int tid  = threadIdx.x;
    const int lane = tid & 31, wid = tid >> 5;
    const int m0 = blockIdx.y * 128, n0 = blockIdx.x * 128;
    const int wm = (wid & 3) * 32, wn = (wid >> 2) * 64;

    const uint32_t sb = smem_to_u32(smem);

    // global load mapping: 512 uint4 per tile; thread covers idx=tid and tid+256
    const int r0g = tid >> 2,         c0g = (tid & 3) * 8;
    const int r1g = (tid + 256) >> 2, c1g = ((tid + 256) & 3) * 8;
    const uint32_t s0 = (uint32_t)(r0g * PB + c0g) * 2;
    const uint32_t s1 = (uint32_t)(r1g * PB + c1g) * 2;

    float acc[2][8][4];
    #pragma unroll
    for (int i = 0; i < 2; i++)
        #pragma unroll
        for (int j = 0; j < 8; j++)
            #pragma unroll
            for (int e = 0; e < 4; e++) acc[i][j][e] = 0.f;

    const int nch = K >> 5;

    auto load_chunk = [&](int c, int buf) {
        const int k0 = c << 5;
        const uint32_t st = sb + buf * STAGE_B;
        const __nv_bfloat16* aH = Ahi  + (size_t)m0 * K + k0;
        const __nv_bfloat16* aL = Alo  + (size_t)m0 * K + k0;
        const __nv_bfloat16* bH = BhiT + (size_t)n0 * K + k0;
        const __nv_bfloat16* bL = BloT + (size_t)n0 * K + k0;
        const size_t g0 = (size_t)r0g * K + c0g;
        const size_t g1 = (size_t)r1g * K + c1g;
        CP_ASYNC16(st + 0*TILE_B + s0, aH + g0);
        CP_ASYNC16(st + 0*TILE_B + s1, aH + g1);
        CP_ASYNC16(st + 1*TILE_B + s0, aL + g0);
        CP_ASYNC16(st + 1*TILE_B + s1, aL + g1);
        CP_ASYNC16(st + 2*TILE_B + s0, bH + g0);
        CP_ASYNC16(st + 2*TILE_B + s1, bH + g1);
        CP_ASYNC16(st + 3*TILE_B + s0, bL + g0);
        CP_ASYNC16(st + 3*TILE_B + s1, bL + g1);
    };

    load_chunk(0, 0);
    CP_COMMIT();

    // per-lane ldmatrix offsets (bytes)
    const uint32_t aoff = (uint32_t)((wm + (lane & 15)) * PB + (lane >> 4) * 8) * 2;
    const uint32_t boff = (uint32_t)((wn + (lane & 7)) * PB + ((lane >> 3) & 1) * 8) * 2;

    for (int c = 0; c < nch; ++c) {
        const int buf = c & 1;
        const bool pre = (c + 1 < nch);
        if (pre) { load_chunk(c + 1, buf ^ 1); CP_COMMIT(); }
        if (pre) CP_WAIT(1); else CP_WAIT(0);
        __syncthreads();

        const uint32_t stA_h = sb + buf * STAGE_B;
        const uint32_t stA_l = stA_h + TILE_B;
        const uint32_t stB_h = stA_h + 2 * TILE_B;
        const uint32_t stB_l = stA_h + 3 * TILE_B;

        #pragma unroll
        for (int ks = 0; ks < 2; ks++) {
            const uint32_t kso = (uint32_t)(ks * 16) * 2;
            uint32_t aH[2][4], aL[2][4];
            #pragma unroll
            for (int i = 0; i < 2; i++) {
                ldmx4(aH[i], stA_h + aoff + kso + (uint32_t)(i * 16 * PB) * 2);
                ldmx4(aL[i], stA_l + aoff + kso + (uint32_t)(i * 16 * PB) * 2);
            }
            #pragma unroll
            for (int jh = 0; jh < 2; jh++) {
                uint32_t bh[4][2], bl[4][2];
                #pragma unroll
                for (int j = 0; j < 4; j++) {
                    const uint32_t jo = (uint32_t)((jh * 4 + j) * 8 * PB) * 2;
                    ldmx2(bh[j], stB_h + boff + kso + jo);
                    ldmx2(bl[j], stB_l + boff + kso + jo);
                }
                #pragma unroll
                for (int i = 0; i < 2; i++)
                    #pragma unroll
                    for (int j = 0; j < 4; j++) {
                        float* a = acc[i][jh * 4 + j];
                        mma16816(a, aH[i], bh[j]);
                        mma16816(a, aH[i], bl[j]);
                        mma16816(a, aL[i], bh[j]);
                    }
            }
        }
        __syncthreads();   // all warps done with buf before it is overwritten
    }

    // -------- epilogue: direct float2 stores --------
    #pragma unroll
    for (int i = 0; i < 2; i++) {
        const int r = m0 + wm + i * 16 + (lane >> 2);
        #pragma unroll
        for (int j = 0; j < 8; j++) {
            const int col = n0 + wn + j * 8 + (lane & 3) * 2;
            float v0 = acc[i][j][0], v1 = acc[i][j][1];
            float v2 = acc[i][j][2], v3 = acc[i][j][3];
            if (MODE >= 1) {
                float2 bb = *(const float2*)(bias + col);
                v0 += bb.x; v1 += bb.y; v2 += bb.x; v3 += bb.y;
            }
            if (MODE == 2) { v0 = gelu_f(v0); v1 = gelu_f(v1); v2 = gelu_f(v2); v3 = gelu_f(v3); }
            if (MODE == 1) {
                float2 r0v = *(const float2*)(res + (size_t)r * N + col);
                float2 r1v = *(const float2*)(res + (size_t)(r + 8) * N + col);
                v0 += r0v.x; v1 += r0v.y; v2 += r1v.x; v3 += r1v.y;
            }
            *(float2*)(C + (size_t)r * N + col)       = make_float2(v0, v1);
            *(float2*)(C + (size_t)(r + 8) * N + col) = make_float2(v2, v3);
        }
    }
}

// ---------------- Flash attention, fp32, causal. Hd=64, 64x64 tiles ----------------
// QKV packed: row stride QKVS, q at +0, k at +1024, v at +2048. O stride DD.
#define ATTN_PITCH 65
#define ATTN_SMEM  (4 * 64 * ATTN_PITCH * 4)

__global__ void __launch_bounds__(256) attn_kernel(
    const float* __restrict__ QKV, float* __restrict__ O)
{
    extern __shared__ float asmem[];
    float* Qs = asmem;
    float* Ks = asmem + 64 * ATTN_PITCH;
    float* Vs = asmem + 2 * 64 * ATTN_PITCH;
    float* Ps = asmem + 3 * 64 * ATTN_PITCH;

    const int bh = blockIdx.y;
    const int b  = bh >> 4, h = bh & 15;
    const int qt = blockIdx.x;
    const int q0 = qt * 64;
    const int tid = threadIdx.x;
    const int tx = tid & 15, ty = tid >> 4;
    const size_t base  = (size_t)b * SS * QKVS + (size_t)h * HD;   // qkv base
    const size_t baseO = (size_t)b * SS * DD   + (size_t)h * HD;

    for (int e = tid; e < 64 * 16; e += 256) {
        int r = e >> 4, c4 = (e & 15) * 4;
        float4 v = *(const float4*)(QKV + base + (size_t)(q0 + r) * QKVS + c4);
        Qs[r * ATTN_PITCH + c4 + 0] = v.x;
        Qs[r * ATTN_PITCH + c4 + 1] = v.y;
        Qs[r * ATTN_PITCH + c4 + 2] = v.z;
        Qs[r * ATTN_PITCH + c4 + 3] = v.w;
    }

    float o[4][4] = {};
    float m[4] = {-1e30f, -1e30f, -1e30f, -1e30f};
    float l[4] = {0.f, 0.f, 0.f, 0.f};

    for (int kt = 0; kt <= qt; kt++) {
        const int k0 = kt * 64;
        __syncthreads();
        for (int e = tid; e < 64 * 16; e += 256) {
            int r = e >> 4, c4 = (e & 15) * 4;
            const size_t rowb = base + (size_t)(k0 + r) * QKVS + c4;
            float4 kv = *(const float4*)(QKV + rowb + 1024);
            Ks[r * ATTN_PITCH + c4 + 0] = kv.x;
            Ks[r * ATTN_PITCH + c4 + 1] = kv.y;
            Ks[r * ATTN_PITCH + c4 + 2] = kv.z;
            Ks[r * ATTN_PITCH + c4 + 3] = kv.w;
            float4 vv = *(const float4*)(QKV + rowb + 2048);
            Vs[r * ATTN_PITCH + c4 + 0] = vv.x;
            Vs[r * ATTN_PITCH + c4 + 1] = vv.y;
            Vs[r * ATTN_PITCH + c4 + 2] = vv.z;
            Vs[r * ATTN_PITCH + c4 + 3] = vv.w;
        }
        __syncthreads();

        float s[4][4] = {};
        #pragma unroll 8
        for (int d = 0; d < 64; d++) {
            float a[4], bb[4];
            #pragma unroll
            for (int r = 0; r < 4; r++) a[r]  = Qs[(ty * 4 + r) * ATTN_PITCH + d];
            #pragma unroll
            for (int c = 0; c < 4; c++) bb[c] = Ks[(tx * 4 + c) * ATTN_PITCH + d];
            #pragma unroll
            for (int r = 0; r < 4; r++)
                #pragma unroll
                for (int c = 0; c < 4; c++)
                    s[r][c] = fmaf(a[r], bb[c], s[r][c]);
        }

        const float sc = 0.125f;
        const bool diag = (kt == qt);
        #pragma unroll
        for (int r = 0; r < 4; r++) {
            const int gi = q0 + ty * 4 + r;
            float mt = -1e30f;
            #pragma unroll
            for (int c = 0; c < 4; c++) {
                float v = s[r][c] * sc;
                if (diag && (k0 + tx * 4 + c) > gi) v = -1e30f;
                s[r][c] = v;
                mt = fmaxf(mt, v);
            }
            #pragma unroll
            for (int off = 8; off; off >>= 1)
                mt = fmaxf(mt, __shfl_xor_sync(0xffffffffu, mt, off));
            const float mnew  = fmaxf(m[r], mt);
            const float alpha = __expf(m[r] - mnew);
            float ps = 0.f;
            #pragma unroll
            for (int c = 0; c < 4; c++) {
                float p = __expf(s[r][c] - mnew);
                Ps[(ty * 4 + r) * ATTN_PITCH + tx * 4 + c] = p;
                ps += p;
            }
            #pragma unroll
            for (int off = 8; off; off >>= 1)
                ps += __shfl_xor_sync(0xffffffffu, ps, off);
            l[r] = l[r] * alpha + ps;
            m[r] = mnew;
            #pragma unroll
            for (int c = 0; c < 4; c++) o[r][c] *= alpha;
        }
        __syncthreads();

        #pragma unroll 8
        for (int d = 0; d < 64; d++) {
            float pa[4], vb[4];
            #pragma unroll
            for (int r = 0; r < 4; r++) pa[r] = Ps[(ty * 4 + r) * ATTN_PITCH + d];
            #pragma unroll
            for (int c = 0; c < 4; c++) vb[c] = Vs[d * ATTN_PITCH + tx * 4 + c];
            #pragma unroll
            for (int r = 0; r < 4; r++)
                #pragma unroll
                for (int c = 0; c < 4; c++)
                    o[r][c] = fmaf(pa[r], vb[c], o[r][c]);
        }
    }

    #pragma unroll
    for (int r = 0; r < 4; r++) {
        const float inv = 1.0f / l[r];
        const int gi = q0 + ty * 4 + r;
        float* op = O + baseO + (size_t)gi * DD + tx * 4;
        #pragma unroll
        for (int c = 0; c < 4; c++) op[c] = o[r][c] * inv;
    }
}

// ---------------- launch ----------------
extern "C" void kernel_launch(void* const* d_in, const int* in_sizes, int n_in,
                              void* d_out, int out_size)
{
    const float* x    = (const float*)d_in[0];
    const float* Wq   = (const float*)d_in[1];
    const float* Wk   = (const float*)d_in[2];
    const float* Wv   = (const float*)d_in[3];
    const float* Wo   = (const float*)d_in[4];
    const float* bo   = (const float*)d_in[5];
    const float* W1   = (const float*)d_in[6];
    const float* b1   = (const float*)d_in[7];
    const float* W2   = (const float*)d_in[8];
    const float* b2   = (const float*)d_in[9];
    const float* ln1s = (const float*)d_in[10];
    const float* ln1b = (const float*)d_in[11];
    const float* ln2s = (const float*)d_in[12];
    const float* ln2b = (const float*)d_in[13];
    float* out = (float*)d_out;

    float *ctx, *x2, *ffn;
    __nv_bfloat16 *ahi, *alo, *whi, *wlo;
    cudaGetSymbolAddress((void**)&ctx, g_ctx);
    cudaGetSymbolAddress((void**)&x2,  g_x2);
    cudaGetSymbolAddress((void**)&ffn, g_ffn);
    cudaGetSymbolAddress((void**)&ahi, g_ahi);
    cudaGetSymbolAddress((void**)&alo, g_alo);
    cudaGetSymbolAddress((void**)&whi, g_whi);
    cudaGetSymbolAddress((void**)&wlo, g_wlo);
    float* qkv = ffn;   // packed q|k|v (ROWS x 3072), dead before ffn is written

    cudaFuncSetAttribute(attn_kernel, cudaFuncAttributeMaxDynamicSharedMemorySize, ATTN_SMEM);
    cudaFuncSetAttribute(mm_gemm<0>, cudaFuncAttributeMaxDynamicSharedMemorySize, MM_SMEM);
    cudaFuncSetAttribute(mm_gemm<1>, cudaFuncAttributeMaxDynamicSharedMemorySize, MM_SMEM);
    cudaFuncSetAttribute(mm_gemm<2>, cudaFuncAttributeMaxDynamicSharedMemorySize, MM_SMEM);

    const dim3 gQKV(QKVS / 128, ROWS / 128);
    const dim3 gD(DD / 128, ROWS / 128);
    const dim3 gF(DFF / 128, ROWS / 128);
    const dim3 tWd(DD / 32, DD / 32);
    const dim3 tW1(DFF / 32, DD / 32);
    const dim3 tW2(DD / 32, DFF / 32);

    // 1) LN1 fused with split
    ln_split<<<ROWS, 256>>>(x, ln1s, ln1b, ahi, alo);

    // 2) pack Wq|Wk|Wv transposed splits, one fused N=3072 GEMM
    wt_split_T<<<tWd, 256>>>(Wq, whi,                wlo,                DD, DD);
    wt_split_T<<<tWd, 256>>>(Wk, whi + 1024*(size_t)DD, wlo + 1024*(size_t)DD, DD, DD);
    wt_split_T<<<tWd, 256>>>(Wv, whi + 2048*(size_t)DD, wlo + 2048*(size_t)DD, DD, DD);
    mm_gemm<0><<<gQKV, 256, MM_SMEM>>>(ahi, alo, whi, wlo, nullptr, nullptr, qkv, QKVS, DD);

    // 3) causal flash attention (packed qkv)
    dim3 gA(SS / 64, BB * HH);
    attn_kernel<<<gA, 256, ATTN_SMEM>>>(qkv, ctx);

    // 4) output projection + bias + residual
    act_split<<<(ROWS * DD) / 1024, 256>>>(ctx, ahi, alo);
    wt_split_T<<<tWd, 256>>>(Wo, whi, wlo, DD, DD);
    mm_gemm<1><<<gD, 256, MM_SMEM>>>(ahi, alo, whi, wlo, bo, x, x2, DD, DD);

    // 5) LN2 fused with split
    ln_split<<<ROWS, 256>>>(x2, ln2s, ln2b, ahi, alo);

    // 6) FFN up + gelu   (writes ffn over dead qkv)
    wt_split_T<<<tW1, 256>>>(W1, whi, wlo, DD, DFF);
    mm_gemm<2><<<gF, 256, MM_SMEM>>>(ahi, alo, whi, wlo, b1, nullptr, ffn, DFF, DD);

    // 7) FFN down + bias + residual -> output
    act_split<<<(ROWS * DFF) / 1024, 256>>>(ffn, ahi, alo);
    wt_split_T<<<tW2, 256>>>(W2, whi, wlo, DFF, DD);
    mm_gemm<1><<<gD, 256, MM_SMEM>>>(ahi, alo, whi, wlo, b2, x2, out, DD, DFF);
}